// round 4
// baseline (speedup 1.0000x reference)
#include <cuda_runtime.h>
#include <math.h>

// Problem constants
#define Bz 512
#define Tt 200
#define Dd 128
#define Hh 512
#define BT (Bz * Tt)          // 102400
#define COMB 768

// ---------------- scratch (static device globals; no runtime allocation) ----------------
__device__ float g_Ax[BT * 256];          // [x_imp || mask], rows n = t*B + b
__device__ float g_Ad[BT * Dd];           // Delta reordered, rows n = t*B + b
__device__ float g_P [BT * 1536];         // precomputed gate pre-acts (z|r|h), + biases
__device__ float g_DH[BT * Hh];           // delta_h
__device__ float g_Wp  [256 * 1536];      // packed [x;m] weights for 3 gates (K-major)
__device__ float g_Pb  [1536];            // packed gate biases
__device__ float g_Wght[Dd * Hh];         // W_gh transposed -> [K=128, N=512]
__device__ float g_Wzr [Hh * 1024];       // h-part of W_z | W_r, [K=512, N=1024]
__device__ float g_Whh [Hh * Hh];         // h-part of W_h,       [K=512, N=512]
__device__ float g_Z [Bz * Hh];           // z gate (sigmoid), per step
__device__ float g_RH[Bz * Hh];           // r * (delta_h*h), per step
__device__ float g_h [2][Bz * Hh];        // double-buffered hidden state

// ---------------- weight packing + h0 init ----------------
__global__ void k_pack(const float* __restrict__ W_z, const float* __restrict__ b_z,
                       const float* __restrict__ W_r, const float* __restrict__ b_r,
                       const float* __restrict__ W_h, const float* __restrict__ b_h,
                       const float* __restrict__ W_gh)
{
    int tid = blockIdx.x * blockDim.x + threadIdx.x;
    int nt  = gridDim.x * blockDim.x;

    // Wp [256 x 1536]: K-major. Rows 0..127 = x part, 128..255 = mask part.
    for (int idx = tid; idx < 256 * 1536; idx += nt) {
        int k = idx / 1536, j = idx % 1536;
        int g = j >> 9, jj = j & 511;
        const float* W = (g == 0) ? W_z : (g == 1) ? W_r : W_h;
        int col = (k < 128) ? k : (640 + (k - 128));
        g_Wp[idx] = W[jj * COMB + col];
    }
    for (int j = tid; j < 1536; j += nt) {
        int g = j >> 9, jj = j & 511;
        g_Pb[j] = (g == 0) ? b_z[jj] : (g == 1) ? b_r[jj] : b_h[jj];
    }
    // W_gh^T : [128 x 512]
    for (int idx = tid; idx < 128 * 512; idx += nt) {
        int k = idx >> 9, j = idx & 511;
        g_Wght[idx] = W_gh[j * 128 + k];
    }
    // h-part of W_z|W_r : [512 x 1024]
    for (int idx = tid; idx < 512 * 1024; idx += nt) {
        int k = idx >> 10, j = idx & 1023;
        g_Wzr[idx] = (j < 512) ? W_z[j * COMB + 128 + k]
                               : W_r[(j - 512) * COMB + 128 + k];
    }
    // h-part of W_h : [512 x 512]
    for (int idx = tid; idx < 512 * 512; idx += nt) {
        int k = idx >> 9, j = idx & 511;
        g_Whh[idx] = W_h[j * COMB + 128 + k];
    }
    // h0 = 0
    for (int idx = tid; idx < Bz * Hh; idx += nt) g_h[0][idx] = 0.f;
}

// ---------------- imputation (elementwise, parallel over B*T*D) ----------------
__global__ void k_impute(const float* __restrict__ X,  const float* __restrict__ XL,
                         const float* __restrict__ M,  const float* __restrict__ Dl,
                         const float* __restrict__ xm, const float* __restrict__ w_gx,
                         const float* __restrict__ b_gx)
{
    int n = blockIdx.x * blockDim.x + threadIdx.x;
    if (n >= BT * Dd) return;
    int nrow = n >> 7, d = n & 127;
    int t = nrow >> 9, b = nrow & 511;
    int src = (b * Tt + t) * Dd + d;
    float dl = Dl[src];
    float m  = M[src];
    float dx = expf(-fmaxf(dl * w_gx[d] + b_gx[d], 0.f));
    float xi = m * X[src] + (1.f - m) * (dx * XL[src] + (1.f - dx) * xm[t * Dd + d]);
    g_Ax[nrow * 256 + d]       = xi;
    g_Ax[nrow * 256 + 128 + d] = m;
    g_Ad[n] = dl;
}

// ---------------- big precompute GEMM: P = A_x @ Wp + Pb   (M=BT, N=1536, K=256) ----------------
__global__ void __launch_bounds__(256) k_gemmP()
{
    __shared__ float As[16][129];
    __shared__ float Bs[16][64];
    int tid = threadIdx.x, tx = tid & 15, ty = tid >> 4;
    int m0 = blockIdx.y * 128, n0 = blockIdx.x * 64;
    float acc[8][4];
    #pragma unroll
    for (int i = 0; i < 8; i++)
        #pragma unroll
        for (int j = 0; j < 4; j++) acc[i][j] = 0.f;

    for (int k0 = 0; k0 < 256; k0 += 16) {
        #pragma unroll
        for (int i = 0; i < 8; i++) {
            int lin = tid + i * 256; int kk = lin & 15, m = lin >> 4;
            As[kk][m] = g_Ax[(size_t)(m0 + m) * 256 + (k0 + kk)];
        }
        #pragma unroll
        for (int i = 0; i < 4; i++) {
            int lin = tid + i * 256; int kk = lin >> 6, nn = lin & 63;
            Bs[kk][nn] = g_Wp[(k0 + kk) * 1536 + n0 + nn];
        }
        __syncthreads();
        #pragma unroll
        for (int kk = 0; kk < 16; kk++) {
            float a[8], bv[4];
            #pragma unroll
            for (int i = 0; i < 8; i++) a[i] = As[kk][ty * 8 + i];
            #pragma unroll
            for (int j = 0; j < 4; j++) bv[j] = Bs[kk][tx * 4 + j];
            #pragma unroll
            for (int i = 0; i < 8; i++)
                #pragma unroll
                for (int j = 0; j < 4; j++) acc[i][j] += a[i] * bv[j];
        }
        __syncthreads();
    }
    #pragma unroll
    for (int i = 0; i < 8; i++) {
        int gm = m0 + ty * 8 + i;
        #pragma unroll
        for (int j = 0; j < 4; j++) {
            int gn = n0 + tx * 4 + j;
            g_P[(size_t)gm * 1536 + gn] = acc[i][j] + g_Pb[gn];
        }
    }
}

// ---------------- delta_h GEMM: DH = exp(-relu(A_d @ Wght + b_gh)) (M=BT, N=512, K=128) ----------------
__global__ void __launch_bounds__(256) k_gemmDH(const float* __restrict__ b_gh)
{
    __shared__ float As[16][129];
    __shared__ float Bs[16][64];
    int tid = threadIdx.x, tx = tid & 15, ty = tid >> 4;
    int m0 = blockIdx.y * 128, n0 = blockIdx.x * 64;
    float acc[8][4];
    #pragma unroll
    for (int i = 0; i < 8; i++)
        #pragma unroll
        for (int j = 0; j < 4; j++) acc[i][j] = 0.f;

    for (int k0 = 0; k0 < 128; k0 += 16) {
        #pragma unroll
        for (int i = 0; i < 8; i++) {
            int lin = tid + i * 256; int kk = lin & 15, m = lin >> 4;
            As[kk][m] = g_Ad[(size_t)(m0 + m) * 128 + (k0 + kk)];
        }
        #pragma unroll
        for (int i = 0; i < 4; i++) {
            int lin = tid + i * 256; int kk = lin >> 6, nn = lin & 63;
            Bs[kk][nn] = g_Wght[(k0 + kk) * 512 + n0 + nn];
        }
        __syncthreads();
        #pragma unroll
        for (int kk = 0; kk < 16; kk++) {
            float a[8], bv[4];
            #pragma unroll
            for (int i = 0; i < 8; i++) a[i] = As[kk][ty * 8 + i];
            #pragma unroll
            for (int j = 0; j < 4; j++) bv[j] = Bs[kk][tx * 4 + j];
            #pragma unroll
            for (int i = 0; i < 8; i++)
                #pragma unroll
                for (int j = 0; j < 4; j++) acc[i][j] += a[i] * bv[j];
        }
        __syncthreads();
    }
    #pragma unroll
    for (int i = 0; i < 8; i++) {
        int gm = m0 + ty * 8 + i;
        #pragma unroll
        for (int j = 0; j < 4; j++) {
            int gn = n0 + tx * 4 + j;
            g_DH[(size_t)gm * 512 + gn] = expf(-fmaxf(acc[i][j] + b_gh[gn], 0.f));
        }
    }
}

// ---------------- step 1: (DH_t * h) @ Wzr  -> z, r*hz   (M=512, N=1024, K=512) ----------------
__global__ void __launch_bounds__(256) k_step1(int t)
{
    __shared__ float As[16][65];
    __shared__ float Bs[16][64];
    int tid = threadIdx.x, tx = tid & 15, ty = tid >> 4;
    int m0 = blockIdx.y * 64, n0 = blockIdx.x * 64;
    const float* hprev = g_h[t & 1];
    const float* dhrow = g_DH + (size_t)t * Bz * Hh;
    const float* Prow  = g_P  + (size_t)t * Bz * 1536;

    float acc[4][4];
    #pragma unroll
    for (int i = 0; i < 4; i++)
        #pragma unroll
        for (int j = 0; j < 4; j++) acc[i][j] = 0.f;

    for (int k0 = 0; k0 < 512; k0 += 16) {
        #pragma unroll
        for (int i = 0; i < 4; i++) {
            int lin = tid + i * 256; int kk = lin & 15, m = lin >> 4;
            int gm = m0 + m, gk = k0 + kk;
            As[kk][m] = dhrow[gm * 512 + gk] * hprev[gm * 512 + gk];
        }
        #pragma unroll
        for (int i = 0; i < 4; i++) {
            int lin = tid + i * 256; int kk = lin >> 6, nn = lin & 63;
            Bs[kk][nn] = g_Wzr[(k0 + kk) * 1024 + n0 + nn];
        }
        __syncthreads();
        #pragma unroll
        for (int kk = 0; kk < 16; kk++) {
            float a[4], bv[4];
            #pragma unroll
            for (int i = 0; i < 4; i++) a[i] = As[kk][ty * 4 + i];
            #pragma unroll
            for (int j = 0; j < 4; j++) bv[j] = Bs[kk][tx * 4 + j];
            #pragma unroll
            for (int i = 0; i < 4; i++)
                #pragma unroll
                for (int j = 0; j < 4; j++) acc[i][j] += a[i] * bv[j];
        }
        __syncthreads();
    }
    #pragma unroll
    for (int i = 0; i < 4; i++) {
        int gm = m0 + ty * 4 + i;
        #pragma unroll
        for (int j = 0; j < 4; j++) {
            int gn = n0 + tx * 4 + j;
            float pre = acc[i][j] + Prow[(size_t)gm * 1536 + gn];
            float s = 1.f / (1.f + expf(-pre));
            if (gn < 512) {
                g_Z[gm * 512 + gn] = s;                 // z gate
            } else {
                int jj = gn - 512;                      // r gate -> r * (dh*h)
                g_RH[gm * 512 + jj] = s * dhrow[gm * 512 + jj] * hprev[gm * 512 + jj];
            }
        }
    }
}

// ---------------- step 2: (r*hz) @ Whh -> h update   (M=512, N=512, K=512) ----------------
__global__ void __launch_bounds__(256) k_step2(int t)
{
    __shared__ float As[16][65];
    __shared__ float Bs[16][32];
    int tid = threadIdx.x, tx = tid & 15, ty = tid >> 4;
    int m0 = blockIdx.y * 64, n0 = blockIdx.x * 32;
    const float* hprev = g_h[t & 1];
    float*       hnext = g_h[(t + 1) & 1];
    const float* dhrow = g_DH + (size_t)t * Bz * Hh;
    const float* Prow  = g_P  + (size_t)t * Bz * 1536;

    float acc[4][2];
    #pragma unroll
    for (int i = 0; i < 4; i++) { acc[i][0] = 0.f; acc[i][1] = 0.f; }

    for (int k0 = 0; k0 < 512; k0 += 16) {
        #pragma unroll
        for (int i = 0; i < 4; i++) {
            int lin = tid + i * 256; int kk = lin & 15, m = lin >> 4;
            As[kk][m] = g_RH[(m0 + m) * 512 + k0 + kk];
        }
        #pragma unroll
        for (int i = 0; i < 2; i++) {
            int lin = tid + i * 256; int kk = lin >> 5, nn = lin & 31;
            Bs[kk][nn] = g_Whh[(k0 + kk) * 512 + n0 + nn];
        }
        __syncthreads();
        #pragma unroll
        for (int kk = 0; kk < 16; kk++) {
            float a[4], b0 = Bs[kk][tx * 2], b1 = Bs[kk][tx * 2 + 1];
            #pragma unroll
            for (int i = 0; i < 4; i++) a[i] = As[kk][ty * 4 + i];
            #pragma unroll
            for (int i = 0; i < 4; i++) { acc[i][0] += a[i] * b0; acc[i][1] += a[i] * b1; }
        }
        __syncthreads();
    }
    #pragma unroll
    for (int i = 0; i < 4; i++) {
        int gm = m0 + ty * 4 + i;
        #pragma unroll
        for (int j = 0; j < 2; j++) {
            int gn = n0 + tx * 2 + j;
            float ht = tanhf(acc[i][j] + Prow[(size_t)gm * 1536 + 1024 + gn]);
            float z  = g_Z[gm * 512 + gn];
            float hz = dhrow[gm * 512 + gn] * hprev[gm * 512 + gn];
            hnext[gm * 512 + gn] = (1.f - z) * hz + z * ht;
        }
    }
}

// ---------------- tail: logits + train-mode BatchNorm over batch ----------------
__global__ void __launch_bounds__(512) k_final(const float* __restrict__ W_fc,
                                               const float* __restrict__ b_fc,
                                               const float* __restrict__ gma,
                                               const float* __restrict__ bta,
                                               float* __restrict__ out)
{
    __shared__ float w0[512], w1[512];
    __shared__ float4 red[512];
    int tid = threadIdx.x;
    w0[tid] = W_fc[tid];
    w1[tid] = W_fc[512 + tid];
    __syncthreads();

    const float* hr = g_h[Tt & 1] + (size_t)tid * 512;   // T even -> final state in buffer 0
    float a0 = 0.f, a1 = 0.f;
    for (int k = 0; k < 512; k++) {
        float v = hr[k];
        a0 += v * w0[k];
        a1 += v * w1[k];
    }
    a0 += b_fc[0];
    a1 += b_fc[1];

    red[tid] = make_float4(a0, a1, a0 * a0, a1 * a1);
    __syncthreads();
    for (int s = 256; s > 0; s >>= 1) {
        if (tid < s) {
            float4 o = red[tid + s];
            red[tid].x += o.x; red[tid].y += o.y;
            red[tid].z += o.z; red[tid].w += o.w;
        }
        __syncthreads();
    }
    float4 tot = red[0];
    float mu0 = tot.x * (1.f / 512.f), mu1 = tot.y * (1.f / 512.f);
    float v0  = tot.z * (1.f / 512.f) - mu0 * mu0;
    float v1  = tot.w * (1.f / 512.f) - mu1 * mu1;
    out[tid * 2 + 0] = gma[0] * (a0 - mu0) * rsqrtf(v0 + 1e-5f) + bta[0];
    out[tid * 2 + 1] = gma[1] * (a1 - mu1) * rsqrtf(v1 + 1e-5f) + bta[1];
}

// ---------------- launcher ----------------
extern "C" void kernel_launch(void* const* d_in, const int* in_sizes, int n_in,
                              void* d_out, int out_size)
{
    (void)in_sizes; (void)n_in; (void)out_size;
    const float* X    = (const float*)d_in[0];
    const float* XL   = (const float*)d_in[1];
    const float* Mk   = (const float*)d_in[2];
    const float* Dl   = (const float*)d_in[3];
    const float* xm   = (const float*)d_in[4];
    const float* w_gx = (const float*)d_in[5];
    const float* b_gx = (const float*)d_in[6];
    const float* W_gh = (const float*)d_in[7];
    const float* b_gh = (const float*)d_in[8];
    const float* W_z  = (const float*)d_in[9];
    const float* b_z  = (const float*)d_in[10];
    const float* W_r  = (const float*)d_in[11];
    const float* b_r  = (const float*)d_in[12];
    const float* W_h  = (const float*)d_in[13];
    const float* b_h  = (const float*)d_in[14];
    const float* W_fc = (const float*)d_in[15];
    const float* b_fc = (const float*)d_in[16];
    const float* gma  = (const float*)d_in[17];
    const float* bta  = (const float*)d_in[18];
    float* out = (float*)d_out;

    k_pack<<<768, 256>>>(W_z, b_z, W_r, b_r, W_h, b_h, W_gh);
    k_impute<<<(BT * Dd + 255) / 256, 256>>>(X, XL, Mk, Dl, xm, w_gx, b_gx);
    k_gemmP <<<dim3(1536 / 64, BT / 128), 256>>>();
    k_gemmDH<<<dim3(512 / 64,  BT / 128), 256>>>(b_gh);

    for (int t = 0; t < Tt; t++) {
        k_step1<<<dim3(1024 / 64, 512 / 64), 256>>>(t);
        k_step2<<<dim3(512 / 32,  512 / 64), 256>>>(t);
    }
    k_final<<<1, 512>>>(W_fc, b_fc, gma, bta, out);
}

// round 5
// speedup vs baseline: 1.0316x; 1.0316x over previous
#include <cuda_runtime.h>
#include <math.h>

// Problem constants
#define Bz 512
#define Tt 200
#define Dd 128
#define Hh 512
#define BT (Bz * Tt)          // 102400
#define COMB 768

// ---------------- scratch (static device globals) ----------------
__device__ float g_Ax[BT * 256];          // [x_imp || mask] tf32-rounded, rows n = t*B + b
__device__ float g_Ad[BT * Dd];           // Delta reordered (tf32-rounded)
__device__ float g_P [BT * 1536];         // precomputed gate pre-acts (z|r|h) + biases (fp32)
__device__ float g_DH[BT * Hh];           // delta_h (fp32)
__device__ float g_Wp  [256 * 1536];      // packed [x;m] weights, K-major, tf32-rounded
__device__ float g_Pb  [1536];            // packed gate biases (fp32)
__device__ float g_Wght[Dd * Hh];         // W_gh^T [K=128, N=512] tf32
__device__ float g_Wzr [Hh * 1024];       // h-part of W_z|W_r [K=512, N=1024] tf32
__device__ float g_Whh [Hh * Hh];         // h-part of W_h [K=512, N=512] tf32
__device__ float g_Z [Bz * Hh];           // z gate (fp32)
__device__ float g_RH[Bz * Hh];           // r*(dh*h), tf32-rounded (step2 A operand)
__device__ float g_h [2][Bz * Hh];        // double-buffered hidden state (fp32)

// ---------------- tf32 helpers ----------------
__device__ __forceinline__ float f2tf(float x) {
    unsigned r; asm("cvt.rna.tf32.f32 %0, %1;" : "=r"(r) : "f"(x));
    return __uint_as_float(r);
}
// D += A(16x8) * B(8x8), tf32 inputs (as fp32 bit patterns), fp32 accumulate
__device__ __forceinline__ void mma8(float* d, const float* a, const float* b) {
    asm volatile(
        "mma.sync.aligned.m16n8k8.row.col.f32.tf32.tf32.f32 "
        "{%0,%1,%2,%3},{%4,%5,%6,%7},{%8,%9},{%0,%1,%2,%3};"
        : "+f"(d[0]), "+f"(d[1]), "+f"(d[2]), "+f"(d[3])
        : "r"(__float_as_uint(a[0])), "r"(__float_as_uint(a[1])),
          "r"(__float_as_uint(a[2])), "r"(__float_as_uint(a[3])),
          "r"(__float_as_uint(b[0])), "r"(__float_as_uint(b[1])));
}

// ---------------- weight packing (tf32 rounding) + h0 init ----------------
__global__ void k_pack(const float* __restrict__ W_z, const float* __restrict__ b_z,
                       const float* __restrict__ W_r, const float* __restrict__ b_r,
                       const float* __restrict__ W_h, const float* __restrict__ b_h,
                       const float* __restrict__ W_gh)
{
    int tid = blockIdx.x * blockDim.x + threadIdx.x;
    int nt  = gridDim.x * blockDim.x;

    for (int idx = tid; idx < 256 * 1536; idx += nt) {
        int k = idx / 1536, j = idx % 1536;
        int g = j >> 9, jj = j & 511;
        const float* W = (g == 0) ? W_z : (g == 1) ? W_r : W_h;
        int col = (k < 128) ? k : (640 + (k - 128));
        g_Wp[idx] = f2tf(W[jj * COMB + col]);
    }
    for (int j = tid; j < 1536; j += nt) {
        int g = j >> 9, jj = j & 511;
        g_Pb[j] = (g == 0) ? b_z[jj] : (g == 1) ? b_r[jj] : b_h[jj];
    }
    for (int idx = tid; idx < 128 * 512; idx += nt) {
        int k = idx >> 9, j = idx & 511;
        g_Wght[idx] = f2tf(W_gh[j * 128 + k]);
    }
    for (int idx = tid; idx < 512 * 1024; idx += nt) {
        int k = idx >> 10, j = idx & 1023;
        g_Wzr[idx] = f2tf((j < 512) ? W_z[j * COMB + 128 + k]
                                    : W_r[(j - 512) * COMB + 128 + k]);
    }
    for (int idx = tid; idx < 512 * 512; idx += nt) {
        int k = idx >> 9, j = idx & 511;
        g_Whh[idx] = f2tf(W_h[j * COMB + 128 + k]);
    }
    for (int idx = tid; idx < Bz * Hh; idx += nt) g_h[0][idx] = 0.f;
}

// ---------------- imputation ----------------
__global__ void k_impute(const float* __restrict__ X,  const float* __restrict__ XL,
                         const float* __restrict__ M,  const float* __restrict__ Dl,
                         const float* __restrict__ xm, const float* __restrict__ w_gx,
                         const float* __restrict__ b_gx)
{
    int n = blockIdx.x * blockDim.x + threadIdx.x;
    if (n >= BT * Dd) return;
    int nrow = n >> 7, d = n & 127;
    int t = nrow >> 9, b = nrow & 511;
    int src = (b * Tt + t) * Dd + d;
    float dl = Dl[src];
    float m  = M[src];
    float dx = expf(-fmaxf(dl * w_gx[d] + b_gx[d], 0.f));
    float xi = m * X[src] + (1.f - m) * (dx * XL[src] + (1.f - dx) * xm[t * Dd + d]);
    g_Ax[nrow * 256 + d]       = f2tf(xi);
    g_Ax[nrow * 256 + 128 + d] = m;          // 0/1 exact in tf32
    g_Ad[n] = f2tf(dl);
}

// ============ big GEMM P = A_x @ Wp + Pb  (M=BT, N=1536, K=256), tf32 MMA ============
// block tile 128x128, 256 threads (8 warps, 2x4), warp tile 64x32
__global__ void __launch_bounds__(256) k_gemmP()
{
    __shared__ float As[128][40];   // stride 40: fp4-aligned, mma-frag friendly
    __shared__ float Bs[32][136];   // stride 136: conflict-free B frag reads
    int tid = threadIdx.x, warp = tid >> 5, lane = tid & 31;
    int g = lane >> 2, tig = lane & 3;
    int wm = (warp >> 2) * 64, wn = (warp & 3) * 32;
    int m0 = blockIdx.y * 128, n0 = blockIdx.x * 128;

    float acc[4][4][4];
    #pragma unroll
    for (int i = 0; i < 4; i++)
        #pragma unroll
        for (int j = 0; j < 4; j++)
            #pragma unroll
            for (int q = 0; q < 4; q++) acc[i][j][q] = 0.f;

    for (int k0 = 0; k0 < 256; k0 += 32) {
        #pragma unroll
        for (int i = 0; i < 4; i++) {
            int idx = tid + i * 256, r = idx >> 3, c4 = idx & 7;
            float4 v = *(const float4*)&g_Ax[(size_t)(m0 + r) * 256 + k0 + c4 * 4];
            *(float4*)&As[r][c4 * 4] = v;
        }
        #pragma unroll
        for (int i = 0; i < 4; i++) {
            int idx = tid + i * 256, r = idx >> 5, c4 = idx & 31;
            float4 v = *(const float4*)&g_Wp[(size_t)(k0 + r) * 1536 + n0 + c4 * 4];
            *(float4*)&Bs[r][c4 * 4] = v;
        }
        __syncthreads();
        #pragma unroll
        for (int kk = 0; kk < 32; kk += 8) {
            float af[4][4], bf[4][2];
            #pragma unroll
            for (int i = 0; i < 4; i++) {
                int row = wm + i * 16 + g;
                af[i][0] = As[row    ][kk + tig];
                af[i][1] = As[row + 8][kk + tig];
                af[i][2] = As[row    ][kk + tig + 4];
                af[i][3] = As[row + 8][kk + tig + 4];
            }
            #pragma unroll
            for (int j = 0; j < 4; j++) {
                bf[j][0] = Bs[kk + tig    ][wn + j * 8 + g];
                bf[j][1] = Bs[kk + tig + 4][wn + j * 8 + g];
            }
            #pragma unroll
            for (int i = 0; i < 4; i++)
                #pragma unroll
                for (int j = 0; j < 4; j++) mma8(acc[i][j], af[i], bf[j]);
        }
        __syncthreads();
    }
    #pragma unroll
    for (int i = 0; i < 4; i++) {
        int r0 = m0 + wm + i * 16 + g;
        #pragma unroll
        for (int j = 0; j < 4; j++) {
            int c0 = n0 + wn + j * 8 + 2 * tig;
            float b0 = g_Pb[c0], b1 = g_Pb[c0 + 1];
            float2 v0 = make_float2(acc[i][j][0] + b0, acc[i][j][1] + b1);
            float2 v1 = make_float2(acc[i][j][2] + b0, acc[i][j][3] + b1);
            *(float2*)&g_P[(size_t)r0 * 1536 + c0]       = v0;
            *(float2*)&g_P[(size_t)(r0 + 8) * 1536 + c0] = v1;
        }
    }
}

// ============ DH = exp(-relu(A_d @ Wght + b_gh))  (M=BT, N=512, K=128) ============
__global__ void __launch_bounds__(256) k_gemmDH(const float* __restrict__ b_gh)
{
    __shared__ float As[128][40];
    __shared__ float Bs[32][136];
    int tid = threadIdx.x, warp = tid >> 5, lane = tid & 31;
    int g = lane >> 2, tig = lane & 3;
    int wm = (warp >> 2) * 64, wn = (warp & 3) * 32;
    int m0 = blockIdx.y * 128, n0 = blockIdx.x * 128;

    float acc[4][4][4];
    #pragma unroll
    for (int i = 0; i < 4; i++)
        #pragma unroll
        for (int j = 0; j < 4; j++)
            #pragma unroll
            for (int q = 0; q < 4; q++) acc[i][j][q] = 0.f;

    for (int k0 = 0; k0 < 128; k0 += 32) {
        #pragma unroll
        for (int i = 0; i < 4; i++) {
            int idx = tid + i * 256, r = idx >> 3, c4 = idx & 7;
            float4 v = *(const float4*)&g_Ad[(size_t)(m0 + r) * 128 + k0 + c4 * 4];
            *(float4*)&As[r][c4 * 4] = v;
        }
        #pragma unroll
        for (int i = 0; i < 4; i++) {
            int idx = tid + i * 256, r = idx >> 5, c4 = idx & 31;
            float4 v = *(const float4*)&g_Wght[(size_t)(k0 + r) * 512 + n0 + c4 * 4];
            *(float4*)&Bs[r][c4 * 4] = v;
        }
        __syncthreads();
        #pragma unroll
        for (int kk = 0; kk < 32; kk += 8) {
            float af[4][4], bf[4][2];
            #pragma unroll
            for (int i = 0; i < 4; i++) {
                int row = wm + i * 16 + g;
                af[i][0] = As[row    ][kk + tig];
                af[i][1] = As[row + 8][kk + tig];
                af[i][2] = As[row    ][kk + tig + 4];
                af[i][3] = As[row + 8][kk + tig + 4];
            }
            #pragma unroll
            for (int j = 0; j < 4; j++) {
                bf[j][0] = Bs[kk + tig    ][wn + j * 8 + g];
                bf[j][1] = Bs[kk + tig + 4][wn + j * 8 + g];
            }
            #pragma unroll
            for (int i = 0; i < 4; i++)
                #pragma unroll
                for (int j = 0; j < 4; j++) mma8(acc[i][j], af[i], bf[j]);
        }
        __syncthreads();
    }
    #pragma unroll
    for (int i = 0; i < 4; i++) {
        int r0 = m0 + wm + i * 16 + g;
        #pragma unroll
        for (int j = 0; j < 4; j++) {
            int c0 = n0 + wn + j * 8 + 2 * tig;
            float b0 = b_gh[c0], b1 = b_gh[c0 + 1];
            g_DH[(size_t)r0 * 512 + c0]           = expf(-fmaxf(acc[i][j][0] + b0, 0.f));
            g_DH[(size_t)r0 * 512 + c0 + 1]       = expf(-fmaxf(acc[i][j][1] + b1, 0.f));
            g_DH[(size_t)(r0 + 8) * 512 + c0]     = expf(-fmaxf(acc[i][j][2] + b0, 0.f));
            g_DH[(size_t)(r0 + 8) * 512 + c0 + 1] = expf(-fmaxf(acc[i][j][3] + b1, 0.f));
        }
    }
}

// ============ step 1: (DH_t*h) @ Wzr -> z, r*hz  (M=512, N=1024, K=512) ============
// block 64x64, 128 threads (4 warps, 2x2), warp tile 32x32
__global__ void __launch_bounds__(128) k_step1(int t)
{
    __shared__ float As[64][40];
    __shared__ float Bs[32][72];
    int tid = threadIdx.x, warp = tid >> 5, lane = tid & 31;
    int g = lane >> 2, tig = lane & 3;
    int wm = (warp >> 1) * 32, wn = (warp & 1) * 32;
    int m0 = blockIdx.y * 64, n0 = blockIdx.x * 64;
    const float* hp = g_h[t & 1];
    const float* dh = g_DH + (size_t)t * Bz * Hh;
    const float* Pr = g_P  + (size_t)t * Bz * 1536;

    float acc[2][4][4];
    #pragma unroll
    for (int i = 0; i < 2; i++)
        #pragma unroll
        for (int j = 0; j < 4; j++)
            #pragma unroll
            for (int q = 0; q < 4; q++) acc[i][j][q] = 0.f;

    for (int k0 = 0; k0 < 512; k0 += 32) {
        #pragma unroll
        for (int i = 0; i < 4; i++) {
            int idx = tid + i * 128, r = idx >> 3, c4 = idx & 7;
            int base = (m0 + r) * 512 + k0 + c4 * 4;
            float4 d4 = *(const float4*)&dh[base];
            float4 h4 = *(const float4*)&hp[base];
            float4 o;
            o.x = f2tf(d4.x * h4.x); o.y = f2tf(d4.y * h4.y);
            o.z = f2tf(d4.z * h4.z); o.w = f2tf(d4.w * h4.w);
            *(float4*)&As[r][c4 * 4] = o;
        }
        #pragma unroll
        for (int i = 0; i < 4; i++) {
            int idx = tid + i * 128, r = idx >> 4, c4 = idx & 15;
            *(float4*)&Bs[r][c4 * 4] =
                *(const float4*)&g_Wzr[(size_t)(k0 + r) * 1024 + n0 + c4 * 4];
        }
        __syncthreads();
        #pragma unroll
        for (int kk = 0; kk < 32; kk += 8) {
            float af[2][4], bf[4][2];
            #pragma unroll
            for (int i = 0; i < 2; i++) {
                int row = wm + i * 16 + g;
                af[i][0] = As[row    ][kk + tig];
                af[i][1] = As[row + 8][kk + tig];
                af[i][2] = As[row    ][kk + tig + 4];
                af[i][3] = As[row + 8][kk + tig + 4];
            }
            #pragma unroll
            for (int j = 0; j < 4; j++) {
                bf[j][0] = Bs[kk + tig    ][wn + j * 8 + g];
                bf[j][1] = Bs[kk + tig + 4][wn + j * 8 + g];
            }
            #pragma unroll
            for (int i = 0; i < 2; i++)
                #pragma unroll
                for (int j = 0; j < 4; j++) mma8(acc[i][j], af[i], bf[j]);
        }
        __syncthreads();
    }

    bool isz = (n0 < 512);   // whole block is z-gate or r-gate (64 | 512)
    #pragma unroll
    for (int i = 0; i < 2; i++) {
        #pragma unroll
        for (int j = 0; j < 4; j++) {
            int c = n0 + wn + j * 8 + 2 * tig;
            #pragma unroll
            for (int rr = 0; rr < 2; rr++) {
                int row = m0 + wm + i * 16 + g + rr * 8;
                #pragma unroll
                for (int cc = 0; cc < 2; cc++) {
                    float pre = acc[i][j][rr * 2 + cc] + Pr[(size_t)row * 1536 + c + cc];
                    float s = 1.f / (1.f + expf(-pre));
                    if (isz) {
                        g_Z[row * 512 + c + cc] = s;
                    } else {
                        int jj = c + cc - 512;
                        g_RH[row * 512 + jj] =
                            f2tf(s * dh[row * 512 + jj] * hp[row * 512 + jj]);
                    }
                }
            }
        }
    }
}

// ============ step 2: RH @ Whh -> h update  (M=512, N=512, K=512) ============
__global__ void __launch_bounds__(128) k_step2(int t)
{
    __shared__ float As[64][40];
    __shared__ float Bs[32][72];
    int tid = threadIdx.x, warp = tid >> 5, lane = tid & 31;
    int g = lane >> 2, tig = lane & 3;
    int wm = (warp >> 1) * 32, wn = (warp & 1) * 32;
    int m0 = blockIdx.y * 64, n0 = blockIdx.x * 64;
    const float* hp = g_h[t & 1];
    float*       hn = g_h[(t + 1) & 1];
    const float* dh = g_DH + (size_t)t * Bz * Hh;
    const float* Pr = g_P  + (size_t)t * Bz * 1536;

    float acc[2][4][4];
    #pragma unroll
    for (int i = 0; i < 2; i++)
        #pragma unroll
        for (int j = 0; j < 4; j++)
            #pragma unroll
            for (int q = 0; q < 4; q++) acc[i][j][q] = 0.f;

    for (int k0 = 0; k0 < 512; k0 += 32) {
        #pragma unroll
        for (int i = 0; i < 4; i++) {
            int idx = tid + i * 128, r = idx >> 3, c4 = idx & 7;
            *(float4*)&As[r][c4 * 4] =
                *(const float4*)&g_RH[(m0 + r) * 512 + k0 + c4 * 4];
        }
        #pragma unroll
        for (int i = 0; i < 4; i++) {
            int idx = tid + i * 128, r = idx >> 4, c4 = idx & 15;
            *(float4*)&Bs[r][c4 * 4] =
                *(const float4*)&g_Whh[(size_t)(k0 + r) * 512 + n0 + c4 * 4];
        }
        __syncthreads();
        #pragma unroll
        for (int kk = 0; kk < 32; kk += 8) {
            float af[2][4], bf[4][2];
            #pragma unroll
            for (int i = 0; i < 2; i++) {
                int row = wm + i * 16 + g;
                af[i][0] = As[row    ][kk + tig];
                af[i][1] = As[row + 8][kk + tig];
                af[i][2] = As[row    ][kk + tig + 4];
                af[i][3] = As[row + 8][kk + tig + 4];
            }
            #pragma unroll
            for (int j = 0; j < 4; j++) {
                bf[j][0] = Bs[kk + tig    ][wn + j * 8 + g];
                bf[j][1] = Bs[kk + tig + 4][wn + j * 8 + g];
            }
            #pragma unroll
            for (int i = 0; i < 2; i++)
                #pragma unroll
                for (int j = 0; j < 4; j++) mma8(acc[i][j], af[i], bf[j]);
        }
        __syncthreads();
    }

    #pragma unroll
    for (int i = 0; i < 2; i++) {
        #pragma unroll
        for (int j = 0; j < 4; j++) {
            int c = n0 + wn + j * 8 + 2 * tig;
            #pragma unroll
            for (int rr = 0; rr < 2; rr++) {
                int row = m0 + wm + i * 16 + g + rr * 8;
                #pragma unroll
                for (int cc = 0; cc < 2; cc++) {
                    int col = c + cc;
                    float ht = tanhf(acc[i][j][rr * 2 + cc] +
                                     Pr[(size_t)row * 1536 + 1024 + col]);
                    float z  = g_Z[row * 512 + col];
                    float hz = dh[row * 512 + col] * hp[row * 512 + col];
                    hn[row * 512 + col] = (1.f - z) * hz + z * ht;
                }
            }
        }
    }
}

// ---------------- tail: logits + train-mode BatchNorm over batch ----------------
__global__ void __launch_bounds__(512) k_final(const float* __restrict__ W_fc,
                                               const float* __restrict__ b_fc,
                                               const float* __restrict__ gma,
                                               const float* __restrict__ bta,
                                               float* __restrict__ out)
{
    __shared__ float w0[512], w1[512];
    __shared__ float4 red[512];
    int tid = threadIdx.x;
    w0[tid] = W_fc[tid];
    w1[tid] = W_fc[512 + tid];
    __syncthreads();

    const float* hr = g_h[Tt & 1] + (size_t)tid * 512;   // T even -> buffer 0
    float a0 = 0.f, a1 = 0.f;
    for (int k = 0; k < 512; k++) {
        float v = hr[k];
        a0 += v * w0[k];
        a1 += v * w1[k];
    }
    a0 += b_fc[0];
    a1 += b_fc[1];

    red[tid] = make_float4(a0, a1, a0 * a0, a1 * a1);
    __syncthreads();
    for (int s = 256; s > 0; s >>= 1) {
        if (tid < s) {
            float4 o = red[tid + s];
            red[tid].x += o.x; red[tid].y += o.y;
            red[tid].z += o.z; red[tid].w += o.w;
        }
        __syncthreads();
    }
    float4 tot = red[0];
    float mu0 = tot.x * (1.f / 512.f), mu1 = tot.y * (1.f / 512.f);
    float v0  = tot.z * (1.f / 512.f) - mu0 * mu0;
    float v1  = tot.w * (1.f / 512.f) - mu1 * mu1;
    out[tid * 2 + 0] = gma[0] * (a0 - mu0) * rsqrtf(v0 + 1e-5f) + bta[0];
    out[tid * 2 + 1] = gma[1] * (a1 - mu1) * rsqrtf(v1 + 1e-5f) + bta[1];
}

// ---------------- launcher ----------------
extern "C" void kernel_launch(void* const* d_in, const int* in_sizes, int n_in,
                              void* d_out, int out_size)
{
    (void)in_sizes; (void)n_in; (void)out_size;
    const float* X    = (const float*)d_in[0];
    const float* XL   = (const float*)d_in[1];
    const float* Mk   = (const float*)d_in[2];
    const float* Dl   = (const float*)d_in[3];
    const float* xm   = (const float*)d_in[4];
    const float* w_gx = (const float*)d_in[5];
    const float* b_gx = (const float*)d_in[6];
    const float* W_gh = (const float*)d_in[7];
    const float* b_gh = (const float*)d_in[8];
    const float* W_z  = (const float*)d_in[9];
    const float* b_z  = (const float*)d_in[10];
    const float* W_r  = (const float*)d_in[11];
    const float* b_r  = (const float*)d_in[12];
    const float* W_h  = (const float*)d_in[13];
    const float* b_h  = (const float*)d_in[14];
    const float* W_fc = (const float*)d_in[15];
    const float* b_fc = (const float*)d_in[16];
    const float* gma  = (const float*)d_in[17];
    const float* bta  = (const float*)d_in[18];
    float* out = (float*)d_out;

    k_pack<<<768, 256>>>(W_z, b_z, W_r, b_r, W_h, b_h, W_gh);
    k_impute<<<(BT * Dd + 255) / 256, 256>>>(X, XL, Mk, Dl, xm, w_gx, b_gx);
    k_gemmP <<<dim3(1536 / 128, BT / 128), 256>>>();
    k_gemmDH<<<dim3(512 / 128,  BT / 128), 256>>>(b_gh);

    for (int t = 0; t < Tt; t++) {
        k_step1<<<dim3(1024 / 64, 512 / 64), 128>>>(t);
        k_step2<<<dim3(512 / 64,  512 / 64), 128>>>(t);
    }
    k_final<<<1, 512>>>(W_fc, b_fc, gma, bta, out);
}

// round 6
// speedup vs baseline: 2.3842x; 2.3112x over previous
#include <cuda_runtime.h>
#include <math.h>

// Problem constants
#define Bz 512
#define Tt 200
#define Dd 128
#define Hh 512
#define BT (Bz * Tt)          // 102400
#define COMB 768
#define NBLK 128              // persistent kernel grid (<= 148 SMs -> all resident)

// ---------------- scratch (static device globals) ----------------
__device__ float g_Ax[BT * 256];          // [x_imp || mask] tf32-rounded
__device__ float g_Ad[BT * Dd];           // Delta reordered (tf32-rounded)
__device__ float g_P [BT * 1536];         // gate pre-acts (z|r|h) + biases (fp32)
__device__ float g_DH[BT * Hh];           // delta_h (fp32)
__device__ float g_Wp  [256 * 1536];      // packed [x;m] weights, K-major, tf32
__device__ float g_Pb  [1536];
__device__ float g_Wght[Dd * Hh];         // W_gh^T [128,512] tf32
__device__ float g_Wzr [Hh * 1024];       // h-part W_z|W_r [512,1024] tf32
__device__ float g_Whh [Hh * Hh];         // h-part W_h [512,512] tf32
__device__ float g_Z [Bz * Hh];           // z gate (fp32)
__device__ float g_RH[Bz * Hh];           // r*(dh*h), tf32 (phase-B A operand)
__device__ float g_HZ[Bz * Hh];           // dh_t * h_{t-1}, tf32 (phase-A A operand)
__device__ float g_h [Bz * Hh];           // hidden state (exact fp32)

// grid barrier state
__device__ volatile unsigned g_bar_gen;
__device__ unsigned g_bar_cnt;

// ---------------- tf32 helpers ----------------
__device__ __forceinline__ float f2tf(float x) {
    unsigned r; asm("cvt.rna.tf32.f32 %0, %1;" : "=r"(r) : "f"(x));
    return __uint_as_float(r);
}
__device__ __forceinline__ void mma8(float* d, const float* a, const float* b) {
    asm volatile(
        "mma.sync.aligned.m16n8k8.row.col.f32.tf32.tf32.f32 "
        "{%0,%1,%2,%3},{%4,%5,%6,%7},{%8,%9},{%0,%1,%2,%3};"
        : "+f"(d[0]), "+f"(d[1]), "+f"(d[2]), "+f"(d[3])
        : "r"(__float_as_uint(a[0])), "r"(__float_as_uint(a[1])),
          "r"(__float_as_uint(a[2])), "r"(__float_as_uint(a[3])),
          "r"(__float_as_uint(b[0])), "r"(__float_as_uint(b[1])));
}

__device__ __forceinline__ void gridbar(unsigned &gen) {
    __syncthreads();
    if (threadIdx.x == 0) {
        __threadfence();
        unsigned t = atomicAdd(&g_bar_cnt, 1u);
        if (t == NBLK - 1) {
            g_bar_cnt = 0;
            __threadfence();
            atomicAdd((unsigned*)&g_bar_gen, 1u);
        } else {
            while (g_bar_gen == gen) { }
        }
        __threadfence();
    }
    gen++;
    __syncthreads();
}

// ---------------- weight packing (tf32 rounding) + state init ----------------
__global__ void k_pack(const float* __restrict__ W_z, const float* __restrict__ b_z,
                       const float* __restrict__ W_r, const float* __restrict__ b_r,
                       const float* __restrict__ W_h, const float* __restrict__ b_h,
                       const float* __restrict__ W_gh)
{
    int tid = blockIdx.x * blockDim.x + threadIdx.x;
    int nt  = gridDim.x * blockDim.x;

    for (int idx = tid; idx < 256 * 1536; idx += nt) {
        int k = idx / 1536, j = idx % 1536;
        int g = j >> 9, jj = j & 511;
        const float* W = (g == 0) ? W_z : (g == 1) ? W_r : W_h;
        int col = (k < 128) ? k : (640 + (k - 128));
        g_Wp[idx] = f2tf(W[jj * COMB + col]);
    }
    for (int j = tid; j < 1536; j += nt) {
        int g = j >> 9, jj = j & 511;
        g_Pb[j] = (g == 0) ? b_z[jj] : (g == 1) ? b_r[jj] : b_h[jj];
    }
    for (int idx = tid; idx < 128 * 512; idx += nt) {
        int k = idx >> 9, j = idx & 511;
        g_Wght[idx] = f2tf(W_gh[j * 128 + k]);
    }
    for (int idx = tid; idx < 512 * 1024; idx += nt) {
        int k = idx >> 10, j = idx & 1023;
        g_Wzr[idx] = f2tf((j < 512) ? W_z[j * COMB + 128 + k]
                                    : W_r[(j - 512) * COMB + 128 + k]);
    }
    for (int idx = tid; idx < 512 * 512; idx += nt) {
        int k = idx >> 9, j = idx & 511;
        g_Whh[idx] = f2tf(W_h[j * COMB + 128 + k]);
    }
    for (int idx = tid; idx < Bz * Hh; idx += nt) { g_h[idx] = 0.f; g_HZ[idx] = 0.f; }
}

// ---------------- imputation ----------------
__global__ void k_impute(const float* __restrict__ X,  const float* __restrict__ XL,
                         const float* __restrict__ M,  const float* __restrict__ Dl,
                         const float* __restrict__ xm, const float* __restrict__ w_gx,
                         const float* __restrict__ b_gx)
{
    int n = blockIdx.x * blockDim.x + threadIdx.x;
    if (n >= BT * Dd) return;
    int nrow = n >> 7, d = n & 127;
    int t = nrow >> 9, b = nrow & 511;
    int src = (b * Tt + t) * Dd + d;
    float dl = Dl[src];
    float m  = M[src];
    float dx = expf(-fmaxf(dl * w_gx[d] + b_gx[d], 0.f));
    float xi = m * X[src] + (1.f - m) * (dx * XL[src] + (1.f - dx) * xm[t * Dd + d]);
    g_Ax[nrow * 256 + d]       = f2tf(xi);
    g_Ax[nrow * 256 + 128 + d] = m;
    g_Ad[n] = f2tf(dl);
}

// ============ big GEMM P = A_x @ Wp + Pb  (M=BT, N=1536, K=256) ============
__global__ void __launch_bounds__(256) k_gemmP()
{
    __shared__ float As[128][40];
    __shared__ float Bs[32][136];
    int tid = threadIdx.x, warp = tid >> 5, lane = tid & 31;
    int g = lane >> 2, tig = lane & 3;
    int wm = (warp >> 2) * 64, wn = (warp & 3) * 32;
    int m0 = blockIdx.y * 128, n0 = blockIdx.x * 128;

    float acc[4][4][4];
    #pragma unroll
    for (int i = 0; i < 4; i++)
        #pragma unroll
        for (int j = 0; j < 4; j++)
            #pragma unroll
            for (int q = 0; q < 4; q++) acc[i][j][q] = 0.f;

    for (int k0 = 0; k0 < 256; k0 += 32) {
        #pragma unroll
        for (int i = 0; i < 4; i++) {
            int idx = tid + i * 256, r = idx >> 3, c4 = idx & 7;
            *(float4*)&As[r][c4 * 4] =
                *(const float4*)&g_Ax[(size_t)(m0 + r) * 256 + k0 + c4 * 4];
        }
        #pragma unroll
        for (int i = 0; i < 4; i++) {
            int idx = tid + i * 256, r = idx >> 5, c4 = idx & 31;
            *(float4*)&Bs[r][c4 * 4] =
                *(const float4*)&g_Wp[(size_t)(k0 + r) * 1536 + n0 + c4 * 4];
        }
        __syncthreads();
        #pragma unroll
        for (int kk = 0; kk < 32; kk += 8) {
            float af[4][4], bf[4][2];
            #pragma unroll
            for (int i = 0; i < 4; i++) {
                int row = wm + i * 16 + g;
                af[i][0] = As[row    ][kk + tig];
                af[i][1] = As[row + 8][kk + tig];
                af[i][2] = As[row    ][kk + tig + 4];
                af[i][3] = As[row + 8][kk + tig + 4];
            }
            #pragma unroll
            for (int j = 0; j < 4; j++) {
                bf[j][0] = Bs[kk + tig    ][wn + j * 8 + g];
                bf[j][1] = Bs[kk + tig + 4][wn + j * 8 + g];
            }
            #pragma unroll
            for (int i = 0; i < 4; i++)
                #pragma unroll
                for (int j = 0; j < 4; j++) mma8(acc[i][j], af[i], bf[j]);
        }
        __syncthreads();
    }
    #pragma unroll
    for (int i = 0; i < 4; i++) {
        int r0 = m0 + wm + i * 16 + g;
        #pragma unroll
        for (int j = 0; j < 4; j++) {
            int c0 = n0 + wn + j * 8 + 2 * tig;
            float b0 = g_Pb[c0], b1 = g_Pb[c0 + 1];
            float2 v0 = make_float2(acc[i][j][0] + b0, acc[i][j][1] + b1);
            float2 v1 = make_float2(acc[i][j][2] + b0, acc[i][j][3] + b1);
            *(float2*)&g_P[(size_t)r0 * 1536 + c0]       = v0;
            *(float2*)&g_P[(size_t)(r0 + 8) * 1536 + c0] = v1;
        }
    }
}

// ============ DH = exp(-relu(A_d @ Wght + b_gh))  (M=BT, N=512, K=128) ============
__global__ void __launch_bounds__(256) k_gemmDH(const float* __restrict__ b_gh)
{
    __shared__ float As[128][40];
    __shared__ float Bs[32][136];
    int tid = threadIdx.x, warp = tid >> 5, lane = tid & 31;
    int g = lane >> 2, tig = lane & 3;
    int wm = (warp >> 2) * 64, wn = (warp & 3) * 32;
    int m0 = blockIdx.y * 128, n0 = blockIdx.x * 128;

    float acc[4][4][4];
    #pragma unroll
    for (int i = 0; i < 4; i++)
        #pragma unroll
        for (int j = 0; j < 4; j++)
            #pragma unroll
            for (int q = 0; q < 4; q++) acc[i][j][q] = 0.f;

    for (int k0 = 0; k0 < 128; k0 += 32) {
        #pragma unroll
        for (int i = 0; i < 4; i++) {
            int idx = tid + i * 256, r = idx >> 3, c4 = idx & 7;
            *(float4*)&As[r][c4 * 4] =
                *(const float4*)&g_Ad[(size_t)(m0 + r) * 128 + k0 + c4 * 4];
        }
        #pragma unroll
        for (int i = 0; i < 4; i++) {
            int idx = tid + i * 256, r = idx >> 5, c4 = idx & 31;
            *(float4*)&Bs[r][c4 * 4] =
                *(const float4*)&g_Wght[(size_t)(k0 + r) * 512 + n0 + c4 * 4];
        }
        __syncthreads();
        #pragma unroll
        for (int kk = 0; kk < 32; kk += 8) {
            float af[4][4], bf[4][2];
            #pragma unroll
            for (int i = 0; i < 4; i++) {
                int row = wm + i * 16 + g;
                af[i][0] = As[row    ][kk + tig];
                af[i][1] = As[row + 8][kk + tig];
                af[i][2] = As[row    ][kk + tig + 4];
                af[i][3] = As[row + 8][kk + tig + 4];
            }
            #pragma unroll
            for (int j = 0; j < 4; j++) {
                bf[j][0] = Bs[kk + tig    ][wn + j * 8 + g];
                bf[j][1] = Bs[kk + tig + 4][wn + j * 8 + g];
            }
            #pragma unroll
            for (int i = 0; i < 4; i++)
                #pragma unroll
                for (int j = 0; j < 4; j++) mma8(acc[i][j], af[i], bf[j]);
        }
        __syncthreads();
    }
    #pragma unroll
    for (int i = 0; i < 4; i++) {
        int r0 = m0 + wm + i * 16 + g;
        #pragma unroll
        for (int j = 0; j < 4; j++) {
            int c0 = n0 + wn + j * 8 + 2 * tig;
            float b0 = b_gh[c0], b1 = b_gh[c0 + 1];
            g_DH[(size_t)r0 * 512 + c0]           = expf(-fmaxf(acc[i][j][0] + b0, 0.f));
            g_DH[(size_t)r0 * 512 + c0 + 1]       = expf(-fmaxf(acc[i][j][1] + b1, 0.f));
            g_DH[(size_t)(r0 + 8) * 512 + c0]     = expf(-fmaxf(acc[i][j][2] + b0, 0.f));
            g_DH[(size_t)(r0 + 8) * 512 + c0 + 1] = expf(-fmaxf(acc[i][j][3] + b1, 0.f));
        }
    }
}

// ============ persistent recurrence kernel: all 200 steps, 1 launch ============
__global__ void __launch_bounds__(256) k_recur()
{
    __shared__ float As[2][64][40];
    __shared__ float Bs[2][32][72];
    int tid = threadIdx.x, warp = tid >> 5, lane = tid & 31;
    int g = lane >> 2, tig = lane & 3;
    int wm = (warp >> 2) * 32;
    int rowblk = blockIdx.x >> 4, colblk = blockIdx.x & 15;
    unsigned gen = g_bar_gen;

    for (int t = 0; t < Tt; t++) {
        const float* Pr  = g_P  + (size_t)t * Bz * 1536;
        const float* dhc = g_DH + (size_t)t * Bz * 512;

        // ---------- phase A: z|r = sigmoid(HZ @ Wzr + P_zr), tile 64x64 ----------
        {
            int m0 = rowblk * 64, n0 = colblk * 64;
            int wn = (warp & 3) * 16;
            float acc[2][2][4];
            #pragma unroll
            for (int i = 0; i < 2; i++)
                #pragma unroll
                for (int j = 0; j < 2; j++)
                    #pragma unroll
                    for (int q = 0; q < 4; q++) acc[i][j][q] = 0.f;

            float4 ra[2], rb[2];
            #pragma unroll
            for (int i = 0; i < 2; i++) {
                int idx = tid + i * 256, r = idx >> 3, c4 = idx & 7;
                ra[i] = *(const float4*)&g_HZ[(m0 + r) * 512 + c4 * 4];
            }
            #pragma unroll
            for (int i = 0; i < 2; i++) {
                int idx = tid + i * 256, r = idx >> 4, c4 = idx & 15;
                rb[i] = *(const float4*)&g_Wzr[(size_t)r * 1024 + n0 + c4 * 4];
            }
            #pragma unroll
            for (int i = 0; i < 2; i++) {
                int idx = tid + i * 256, r = idx >> 3, c4 = idx & 7;
                *(float4*)&As[0][r][c4 * 4] = ra[i];
            }
            #pragma unroll
            for (int i = 0; i < 2; i++) {
                int idx = tid + i * 256, r = idx >> 4, c4 = idx & 15;
                *(float4*)&Bs[0][r][c4 * 4] = rb[i];
            }
            __syncthreads();

            for (int k0 = 0; k0 < 16; k0++) {
                int cur = k0 & 1;
                if (k0 < 15) {
                    int kb = (k0 + 1) * 32;
                    #pragma unroll
                    for (int i = 0; i < 2; i++) {
                        int idx = tid + i * 256, r = idx >> 3, c4 = idx & 7;
                        ra[i] = *(const float4*)&g_HZ[(m0 + r) * 512 + kb + c4 * 4];
                    }
                    #pragma unroll
                    for (int i = 0; i < 2; i++) {
                        int idx = tid + i * 256, r = idx >> 4, c4 = idx & 15;
                        rb[i] = *(const float4*)&g_Wzr[(size_t)(kb + r) * 1024 + n0 + c4 * 4];
                    }
                }
                #pragma unroll
                for (int kk = 0; kk < 32; kk += 8) {
                    float af[2][4], bf[2][2];
                    #pragma unroll
                    for (int i = 0; i < 2; i++) {
                        int row = wm + i * 16 + g;
                        af[i][0] = As[cur][row    ][kk + tig];
                        af[i][1] = As[cur][row + 8][kk + tig];
                        af[i][2] = As[cur][row    ][kk + tig + 4];
                        af[i][3] = As[cur][row + 8][kk + tig + 4];
                    }
                    #pragma unroll
                    for (int j = 0; j < 2; j++) {
                        int col = wn + j * 8 + g;
                        bf[j][0] = Bs[cur][kk + tig    ][col];
                        bf[j][1] = Bs[cur][kk + tig + 4][col];
                    }
                    #pragma unroll
                    for (int i = 0; i < 2; i++)
                        #pragma unroll
                        for (int j = 0; j < 2; j++) mma8(acc[i][j], af[i], bf[j]);
                }
                if (k0 < 15) {
                    int nxt = cur ^ 1;
                    #pragma unroll
                    for (int i = 0; i < 2; i++) {
                        int idx = tid + i * 256, r = idx >> 3, c4 = idx & 7;
                        *(float4*)&As[nxt][r][c4 * 4] = ra[i];
                    }
                    #pragma unroll
                    for (int i = 0; i < 2; i++) {
                        int idx = tid + i * 256, r = idx >> 4, c4 = idx & 15;
                        *(float4*)&Bs[nxt][r][c4 * 4] = rb[i];
                    }
                }
                __syncthreads();
            }

            bool isz = (n0 < 512);
            #pragma unroll
            for (int i = 0; i < 2; i++) {
                #pragma unroll
                for (int j = 0; j < 2; j++) {
                    int cbase = n0 + wn + j * 8 + 2 * tig;
                    #pragma unroll
                    for (int rr = 0; rr < 2; rr++) {
                        int row = m0 + wm + i * 16 + g + rr * 8;
                        #pragma unroll
                        for (int cc = 0; cc < 2; cc++) {
                            int c = cbase + cc;
                            float pre = acc[i][j][rr * 2 + cc] + Pr[(size_t)row * 1536 + c];
                            float s = 1.f / (1.f + expf(-pre));
                            if (isz) {
                                g_Z[row * 512 + c] = s;
                            } else {
                                int jj = c - 512;
                                g_RH[row * 512 + jj] = f2tf(s * g_HZ[row * 512 + jj]);
                            }
                        }
                    }
                }
            }
        }
        gridbar(gen);

        // ---------- phase B: h update, tile 64x32 ----------
        {
            int m0 = rowblk * 64, n0 = colblk * 32;
            int wn = (warp & 3) * 8;
            float acc[2][4];
            #pragma unroll
            for (int i = 0; i < 2; i++)
                #pragma unroll
                for (int q = 0; q < 4; q++) acc[i][q] = 0.f;

            float4 ra[2], rb;
            #pragma unroll
            for (int i = 0; i < 2; i++) {
                int idx = tid + i * 256, r = idx >> 3, c4 = idx & 7;
                ra[i] = *(const float4*)&g_RH[(m0 + r) * 512 + c4 * 4];
            }
            {
                int r = tid >> 3, c4 = tid & 7;
                rb = *(const float4*)&g_Whh[(size_t)r * 512 + n0 + c4 * 4];
            }
            #pragma unroll
            for (int i = 0; i < 2; i++) {
                int idx = tid + i * 256, r = idx >> 3, c4 = idx & 7;
                *(float4*)&As[0][r][c4 * 4] = ra[i];
            }
            {
                int r = tid >> 3, c4 = tid & 7;
                *(float4*)&Bs[0][r][c4 * 4] = rb;
            }
            __syncthreads();

            for (int k0 = 0; k0 < 16; k0++) {
                int cur = k0 & 1;
                if (k0 < 15) {
                    int kb = (k0 + 1) * 32;
                    #pragma unroll
                    for (int i = 0; i < 2; i++) {
                        int idx = tid + i * 256, r = idx >> 3, c4 = idx & 7;
                        ra[i] = *(const float4*)&g_RH[(m0 + r) * 512 + kb + c4 * 4];
                    }
                    int r = tid >> 3, c4 = tid & 7;
                    rb = *(const float4*)&g_Whh[(size_t)(kb + r) * 512 + n0 + c4 * 4];
                }
                #pragma unroll
                for (int kk = 0; kk < 32; kk += 8) {
                    float af[2][4], bf[2];
                    #pragma unroll
                    for (int i = 0; i < 2; i++) {
                        int row = wm + i * 16 + g;
                        af[i][0] = As[cur][row    ][kk + tig];
                        af[i][1] = As[cur][row + 8][kk + tig];
                        af[i][2] = As[cur][row    ][kk + tig + 4];
                        af[i][3] = As[cur][row + 8][kk + tig + 4];
                    }
                    int col = wn + g;
                    bf[0] = Bs[cur][kk + tig    ][col];
                    bf[1] = Bs[cur][kk + tig + 4][col];
                    #pragma unroll
                    for (int i = 0; i < 2; i++) mma8(acc[i], af[i], bf);
                }
                if (k0 < 15) {
                    int nxt = cur ^ 1;
                    #pragma unroll
                    for (int i = 0; i < 2; i++) {
                        int idx = tid + i * 256, r = idx >> 3, c4 = idx & 7;
                        *(float4*)&As[nxt][r][c4 * 4] = ra[i];
                    }
                    int r = tid >> 3, c4 = tid & 7;
                    *(float4*)&Bs[nxt][r][c4 * 4] = rb;
                }
                __syncthreads();
            }

            const float* dhn = g_DH + (size_t)(t + 1) * Bz * 512;
            #pragma unroll
            for (int i = 0; i < 2; i++) {
                int cbase = n0 + wn + 2 * tig;
                #pragma unroll
                for (int rr = 0; rr < 2; rr++) {
                    int row = m0 + wm + i * 16 + g + rr * 8;
                    #pragma unroll
                    for (int cc = 0; cc < 2; cc++) {
                        int col = cbase + cc;
                        float ht = tanhf(acc[i][rr * 2 + cc] +
                                         Pr[(size_t)row * 1536 + 1024 + col]);
                        float z  = g_Z[row * 512 + col];
                        float hp = g_h[row * 512 + col];
                        float hz = dhc[row * 512 + col] * hp;
                        float hn = (1.f - z) * hz + z * ht;
                        g_h[row * 512 + col] = hn;
                        if (t < Tt - 1)
                            g_HZ[row * 512 + col] = f2tf(dhn[row * 512 + col] * hn);
                    }
                }
            }
        }
        gridbar(gen);
    }
}

// ---------------- tail: logits + train-mode BatchNorm over batch ----------------
__global__ void __launch_bounds__(512) k_final(const float* __restrict__ W_fc,
                                               const float* __restrict__ b_fc,
                                               const float* __restrict__ gma,
                                               const float* __restrict__ bta,
                                               float* __restrict__ out)
{
    __shared__ float w0[512], w1[512];
    __shared__ float4 red[512];
    int tid = threadIdx.x;
    w0[tid] = W_fc[tid];
    w1[tid] = W_fc[512 + tid];
    __syncthreads();

    const float* hr = g_h + (size_t)tid * 512;
    float a0 = 0.f, a1 = 0.f;
    for (int k = 0; k < 512; k++) {
        float v = hr[k];
        a0 += v * w0[k];
        a1 += v * w1[k];
    }
    a0 += b_fc[0];
    a1 += b_fc[1];

    red[tid] = make_float4(a0, a1, a0 * a0, a1 * a1);
    __syncthreads();
    for (int s = 256; s > 0; s >>= 1) {
        if (tid < s) {
            float4 o = red[tid + s];
            red[tid].x += o.x; red[tid].y += o.y;
            red[tid].z += o.z; red[tid].w += o.w;
        }
        __syncthreads();
    }
    float4 tot = red[0];
    float mu0 = tot.x * (1.f / 512.f), mu1 = tot.y * (1.f / 512.f);
    float v0  = tot.z * (1.f / 512.f) - mu0 * mu0;
    float v1  = tot.w * (1.f / 512.f) - mu1 * mu1;
    out[tid * 2 + 0] = gma[0] * (a0 - mu0) * rsqrtf(v0 + 1e-5f) + bta[0];
    out[tid * 2 + 1] = gma[1] * (a1 - mu1) * rsqrtf(v1 + 1e-5f) + bta[1];
}

// ---------------- launcher ----------------
extern "C" void kernel_launch(void* const* d_in, const int* in_sizes, int n_in,
                              void* d_out, int out_size)
{
    (void)in_sizes; (void)n_in; (void)out_size;
    const float* X    = (const float*)d_in[0];
    const float* XL   = (const float*)d_in[1];
    const float* Mk   = (const float*)d_in[2];
    const float* Dl   = (const float*)d_in[3];
    const float* xm   = (const float*)d_in[4];
    const float* w_gx = (const float*)d_in[5];
    const float* b_gx = (const float*)d_in[6];
    const float* W_gh = (const float*)d_in[7];
    const float* b_gh = (const float*)d_in[8];
    const float* W_z  = (const float*)d_in[9];
    const float* b_z  = (const float*)d_in[10];
    const float* W_r  = (const float*)d_in[11];
    const float* b_r  = (const float*)d_in[12];
    const float* W_h  = (const float*)d_in[13];
    const float* b_h  = (const float*)d_in[14];
    const float* W_fc = (const float*)d_in[15];
    const float* b_fc = (const float*)d_in[16];
    const float* gma  = (const float*)d_in[17];
    const float* bta  = (const float*)d_in[18];
    float* out = (float*)d_out;

    k_pack<<<768, 256>>>(W_z, b_z, W_r, b_r, W_h, b_h, W_gh);
    k_impute<<<(BT * Dd + 255) / 256, 256>>>(X, XL, Mk, Dl, xm, w_gx, b_gx);
    k_gemmP <<<dim3(1536 / 128, BT / 128), 256>>>();
    k_gemmDH<<<dim3(512 / 128,  BT / 128), 256>>>(b_gh);
    k_recur <<<NBLK, 256>>>();
    k_final <<<1, 512>>>(W_fc, b_fc, gma, bta, out);
}